// round 6
// baseline (speedup 1.0000x reference)
#include <cuda_runtime.h>
#include <cstdint>

#define Bsz  8192
#define INs  1024
#define H1s  2048
#define H2s  2048
#define OUTs 1024
#define Pex  8

// Scratch (device globals: allocation-free per harness rules)
__device__ float g_h1[(size_t)Bsz * H1s];            // 64 MB (full fp32)
__device__ float g_h2[(size_t)Bsz * H2s];            // 64 MB (tf32-rounded)
__device__ float g_p1[(size_t)Bsz * Pex];
__device__ float g_p2[(size_t)Bsz * Pex];
__device__ float g_xe[(size_t)Bsz * Pex * INs];      // 256 MB expanded A, layer1
__device__ float g_h1e[(size_t)Bsz * Pex * H1s];     // 512 MB expanded A, layer2
__device__ float g_w1r[(size_t)Pex * INs * H1s];     // 64 MB
__device__ float g_w2r[(size_t)Pex * H1s * H2s];     // 128 MB
__device__ float g_wcr[(size_t)H2s * OUTs];          // 8 MB

// ------------------------------ helpers ---------------------------------
__device__ __forceinline__ uint32_t smem_u32(const void* p) {
  uint32_t a;
  asm("{ .reg .u64 t; cvta.to.shared.u64 t, %1; cvt.u32.u64 %0, t; }"
      : "=r"(a) : "l"(p));
  return a;
}
__device__ __forceinline__ void cpa16(uint32_t s, const void* g) {
  asm volatile("cp.async.cg.shared.global [%0], [%1], 16;" :: "r"(s), "l"(g));
}
__device__ __forceinline__ void cpa_commit() {
  asm volatile("cp.async.commit_group;" ::: "memory");
}
template <int N>
__device__ __forceinline__ void cpa_wait() {
  asm volatile("cp.async.wait_group %0;" :: "n"(N) : "memory");
}
__device__ __forceinline__ uint32_t f2tf32(float f) {
  uint32_t u;
  asm("cvt.rna.tf32.f32 %0, %1;" : "=r"(u) : "f"(f));
  return u;
}
__device__ __forceinline__ float rtf(float f) {
  return __uint_as_float(f2tf32(f));
}
__device__ __forceinline__ void ldsm4(uint32_t (&r)[4], uint32_t a) {
  asm volatile("ldmatrix.sync.aligned.m8n8.x4.shared.b16 {%0,%1,%2,%3}, [%4];"
               : "=r"(r[0]), "=r"(r[1]), "=r"(r[2]), "=r"(r[3]) : "r"(a));
}
__device__ __forceinline__ void mma_t(float (&c)[4], const uint32_t (&a)[4],
                                      uint32_t b0, uint32_t b1) {
  asm volatile(
      "mma.sync.aligned.m16n8k8.row.col.f32.tf32.tf32.f32 "
      "{%0,%1,%2,%3}, {%4,%5,%6,%7}, {%8,%9}, {%0,%1,%2,%3};"
      : "+f"(c[0]), "+f"(c[1]), "+f"(c[2]), "+f"(c[3])
      : "r"(a[0]), "r"(a[1]), "r"(a[2]), "r"(a[3]), "r"(b0), "r"(b1));
}

// -------------------------------------------------------------------------
// tf32 pre-round pass (weights)
// -------------------------------------------------------------------------
__global__ void round_tf32_kernel(const float4* __restrict__ in,
                                  float4* __restrict__ out, int n4) {
  int i = blockIdx.x * blockDim.x + threadIdx.x;
  if (i < n4) {
    float4 v = in[i];
    v.x = rtf(v.x); v.y = rtf(v.y); v.z = rtf(v.z); v.w = rtf(v.w);
    out[i] = v;
  }
}

// -------------------------------------------------------------------------
// Expand + scale + round: out[b, p*IN+i] = rna_tf32( X[b,i] * probs[b,p] )
// -------------------------------------------------------------------------
__global__ void expand_scale_kernel(const float4* __restrict__ X,
                                    const float* __restrict__ probs,
                                    float4* __restrict__ out, int in4) {
  int idx = blockIdx.x * blockDim.x + threadIdx.x;   // over B * in4
  int b = idx / in4, i = idx - b * in4;
  float4 v = X[idx];
  const float* pb = probs + (size_t)b * 8;
  size_t ob = (size_t)b * 8 * in4 + i;
#pragma unroll
  for (int p = 0; p < 8; p++) {
    float pr = pb[p];
    float4 o;
    o.x = rtf(v.x * pr); o.y = rtf(v.y * pr);
    o.z = rtf(v.z * pr); o.w = rtf(v.w * pr);
    out[ob + (size_t)p * in4] = o;
  }
}

// -------------------------------------------------------------------------
// Selector: probs[b,:] = softmax(x[b,:] @ S + sb), P = 8. One warp per row.
// -------------------------------------------------------------------------
__global__ void selector_kernel(const float* __restrict__ X,
                                const float* __restrict__ S,
                                const float* __restrict__ sb,
                                float* __restrict__ probs, int K) {
  int warp = (blockIdx.x * blockDim.x + threadIdx.x) >> 5;
  int lane = threadIdx.x & 31;
  const float4* Xv = reinterpret_cast<const float4*>(X + (size_t)warp * K);
  float acc[8];
#pragma unroll
  for (int p = 0; p < 8; p++) acc[p] = 0.f;
  int nvec = K >> 2;
  for (int v = lane; v < nvec; v += 32) {
    float4 x4 = Xv[v];
    const float4* Sv = reinterpret_cast<const float4*>(S + ((size_t)v << 2) * 8);
    float4 s0 = Sv[0], s1 = Sv[1], s2 = Sv[2], s3 = Sv[3];
    float4 s4 = Sv[4], s5 = Sv[5], s6 = Sv[6], s7 = Sv[7];
    acc[0] += x4.x * s0.x + x4.y * s2.x + x4.z * s4.x + x4.w * s6.x;
    acc[1] += x4.x * s0.y + x4.y * s2.y + x4.z * s4.y + x4.w * s6.y;
    acc[2] += x4.x * s0.z + x4.y * s2.z + x4.z * s4.z + x4.w * s6.z;
    acc[3] += x4.x * s0.w + x4.y * s2.w + x4.z * s4.w + x4.w * s6.w;
    acc[4] += x4.x * s1.x + x4.y * s3.x + x4.z * s5.x + x4.w * s7.x;
    acc[5] += x4.x * s1.y + x4.y * s3.y + x4.z * s5.y + x4.w * s7.y;
    acc[6] += x4.x * s1.z + x4.y * s3.z + x4.z * s5.z + x4.w * s7.z;
    acc[7] += x4.x * s1.w + x4.y * s3.w + x4.z * s5.w + x4.w * s7.w;
  }
#pragma unroll
  for (int off = 16; off; off >>= 1)
#pragma unroll
    for (int p = 0; p < 8; p++)
      acc[p] += __shfl_xor_sync(0xffffffffu, acc[p], off);
  if (lane == 0) {
    float m = -1e30f;
#pragma unroll
    for (int p = 0; p < 8; p++) { acc[p] += sb[p]; m = fmaxf(m, acc[p]); }
    float s = 0.f;
#pragma unroll
    for (int p = 0; p < 8; p++) { acc[p] = __expf(acc[p] - m); s += acc[p]; }
    float inv = 1.f / s;
#pragma unroll
    for (int p = 0; p < 8; p++) probs[(size_t)warp * 8 + p] = acc[p] * inv;
  }
}

// -------------------------------------------------------------------------
// Plain mma.sync tf32 GEMM, tile 128x128x32, 3-stage cp.async, 8 warps.
//   MOEBIAS: epilogue adds sum_p probs[m,p]*bias[p,n]; else bias[n].
//   RELU / ROUND applied at store.
// -------------------------------------------------------------------------
template <bool MOEBIAS, bool RELU, bool ROUND>
__global__ __launch_bounds__(256, 2) void tc_gemm(
    int N, int K,
    const float* __restrict__ X, const float* __restrict__ W,
    const float* __restrict__ probs, const float* __restrict__ bias,
    float* __restrict__ C) {
  constexpr int NST = 3;
  constexpr int BROW_F = 136;                    // conflict-free pad (mod 32 = 8)
  constexpr int BSTART_F = 4096;                 // A: 128*32 floats
  constexpr int SSTRIDE_F = BSTART_F + 32 * BROW_F;   // 8448 floats/stage

  extern __shared__ float smf[];
  __shared__ float probs_s[128][8];
  __shared__ float bias_s[8][128];

  const int tid = threadIdx.x, lane = tid & 31, wid = tid >> 5;
  const int wm = wid >> 2, wn = wid & 3;
  const int m0 = blockIdx.y * 128, n0 = blockIdx.x * 128;
  const uint32_t sbase = smem_u32(smf);

  if (MOEBIAS) {
    for (int i = tid; i < 1024; i += 256) {
      int r = i >> 3, p = i & 7;
      probs_s[r][p] = probs[(size_t)(m0 + r) * 8 + p];
    }
    for (int i = tid; i < 1024; i += 256) {
      int p = i >> 7, c = i & 127;
      bias_s[p][c] = bias[(size_t)p * N + n0 + c];
    }
  } else {
    if (tid < 128) bias_s[0][tid] = bias[n0 + tid];
  }

  const int nchunk = K >> 5;

  auto issue = [&](int c, int st) {
    const int k0 = c << 5;
    const uint32_t sA = sbase + (uint32_t)st * (SSTRIDE_F * 4);
    const uint32_t sB = sA + BSTART_F * 4;
    const float* ab = X + k0;
#pragma unroll
    for (int i = 0; i < 4; i++) {          // A: 128 x 32, SW128 swizzle
      int f = tid + i * 256;
      int m = f >> 3, g = f & 7;
      cpa16(sA + (uint32_t)(m * 128 + ((g ^ (m & 7)) << 4)),
            ab + (size_t)(m0 + m) * K + g * 4);
    }
#pragma unroll
    for (int i = 0; i < 4; i++) {          // B: 32 x 128, pad-136 rows
      int f = tid + i * 256;
      int k = f >> 5, nc = f & 31;
      cpa16(sB + (uint32_t)(k * (BROW_F * 4) + nc * 16),
            W + (size_t)(k0 + k) * N + n0 + nc * 4);
    }
    cpa_commit();
  };

  float cacc[4][4][4];
#pragma unroll
  for (int a = 0; a < 4; a++)
#pragma unroll
    for (int b = 0; b < 4; b++)
#pragma unroll
      for (int d = 0; d < 4; d++) cacc[a][b][d] = 0.f;

  // ldmatrix per-thread address components
  const int q = lane >> 3, r8v = lane & 7, qh = q >> 1;
  uint32_t arow[4];
  int arow7[4];
#pragma unroll
  for (int mt = 0; mt < 4; mt++) {
    int r = wm * 64 + mt * 16 + (q & 1) * 8 + r8v;
    arow[mt] = (uint32_t)r * 128u;
    arow7[mt] = r & 7;
  }
  const int grp = lane >> 2, tig = lane & 3;

  issue(0, 0);
  issue(1, 1);

  int st = 0;
  for (int c = 0; c < nchunk; c++) {
    cpa_wait<1>();
    __syncthreads();
    {
      int cn = c + 2;
      if (cn < nchunk) {
        int stn = st + 2; if (stn >= NST) stn -= NST;
        issue(cn, stn);
      } else {
        cpa_commit();
      }
    }
    const uint32_t sA = sbase + (uint32_t)st * (SSTRIDE_F * 4);
    const float* sBf = smf + st * SSTRIDE_F + BSTART_F;
#pragma unroll
    for (int ks = 0; ks < 4; ks++) {
      uint32_t af[4][4];
#pragma unroll
      for (int mt = 0; mt < 4; mt++)
        ldsm4(af[mt], sA + arow[mt] +
                          (uint32_t)(((ks * 2 + qh) ^ arow7[mt]) << 4));
      uint32_t bf[4][2];
#pragma unroll
      for (int nt = 0; nt < 4; nt++) {
        int n = wn * 32 + nt * 8 + grp;
        bf[nt][0] = __float_as_uint(sBf[(ks * 8 + tig) * BROW_F + n]);
        bf[nt][1] = __float_as_uint(sBf[(ks * 8 + tig + 4) * BROW_F + n]);
      }
#pragma unroll
      for (int mt = 0; mt < 4; mt++)
#pragma unroll
        for (int nt = 0; nt < 4; nt++)
          mma_t(cacc[mt][nt], af[mt], bf[nt][0], bf[nt][1]);
    }
    st++; if (st >= NST) st = 0;
  }

  // ---- epilogue ----
#pragma unroll
  for (int mt = 0; mt < 4; mt++) {
#pragma unroll
    for (int half = 0; half < 2; half++) {
      int r = wm * 64 + mt * 16 + grp + half * 8;
      int m = m0 + r;
      float prr[8];
      if (MOEBIAS) {
#pragma unroll
        for (int p = 0; p < 8; p++) prr[p] = probs_s[r][p];
      }
#pragma unroll
      for (int nt = 0; nt < 4; nt++) {
        int nloc = wn * 32 + nt * 8 + tig * 2;
        float v0 = cacc[mt][nt][half * 2 + 0];
        float v1 = cacc[mt][nt][half * 2 + 1];
        if (MOEBIAS) {
          float cb0 = 0.f, cb1 = 0.f;
#pragma unroll
          for (int p = 0; p < 8; p++) {
            cb0 += prr[p] * bias_s[p][nloc];
            cb1 += prr[p] * bias_s[p][nloc + 1];
          }
          v0 += cb0; v1 += cb1;
        } else {
          v0 += bias_s[0][nloc];
          v1 += bias_s[0][nloc + 1];
        }
        if (RELU) { v0 = fmaxf(v0, 0.f); v1 = fmaxf(v1, 0.f); }
        if (ROUND) { v0 = rtf(v0); v1 = rtf(v1); }
        float2 o; o.x = v0; o.y = v1;
        *reinterpret_cast<float2*>(&C[(size_t)m * N + n0 + nloc]) = o;
      }
    }
  }
}

// -------------------------------------------------------------------------
extern "C" void kernel_launch(void* const* d_in, const int* in_sizes, int n_in,
                              void* d_out, int out_size) {
  const float* x   = (const float*)d_in[0];
  const float* W1  = (const float*)d_in[1];
  const float* b1  = (const float*)d_in[2];
  const float* S1  = (const float*)d_in[3];
  const float* sb1 = (const float*)d_in[4];
  const float* W2  = (const float*)d_in[5];
  const float* b2  = (const float*)d_in[6];
  const float* S2  = (const float*)d_in[7];
  const float* sb2 = (const float*)d_in[8];
  const float* Wc  = (const float*)d_in[9];
  const float* bc  = (const float*)d_in[10];
  float* out = (float*)d_out;

  float *h1, *h2, *p1, *p2, *xe, *h1e, *w1r, *w2r, *wcr;
  cudaGetSymbolAddress((void**)&h1, g_h1);
  cudaGetSymbolAddress((void**)&h2, g_h2);
  cudaGetSymbolAddress((void**)&p1, g_p1);
  cudaGetSymbolAddress((void**)&p2, g_p2);
  cudaGetSymbolAddress((void**)&xe, g_xe);
  cudaGetSymbolAddress((void**)&h1e, g_h1e);
  cudaGetSymbolAddress((void**)&w1r, g_w1r);
  cudaGetSymbolAddress((void**)&w2r, g_w2r);
  cudaGetSymbolAddress((void**)&wcr, g_wcr);

  const int SMEM_DYN = 3 * 8448 * 4;   // 101376 B
  cudaFuncSetAttribute(tc_gemm<true, true, false>,
                       cudaFuncAttributeMaxDynamicSharedMemorySize, SMEM_DYN);
  cudaFuncSetAttribute(tc_gemm<true, true, true>,
                       cudaFuncAttributeMaxDynamicSharedMemorySize, SMEM_DYN);
  cudaFuncSetAttribute(tc_gemm<false, false, false>,
                       cudaFuncAttributeMaxDynamicSharedMemorySize, SMEM_DYN);

  // weight tf32 pre-round
  {
    int n4;
    n4 = (Pex * INs * H1s) / 4;
    round_tf32_kernel<<<n4 / 256, 256>>>((const float4*)W1, (float4*)w1r, n4);
    n4 = (Pex * H1s * H2s) / 4;
    round_tf32_kernel<<<n4 / 256, 256>>>((const float4*)W2, (float4*)w2r, n4);
    n4 = (H2s * OUTs) / 4;
    round_tf32_kernel<<<n4 / 256, 256>>>((const float4*)Wc, (float4*)wcr, n4);
  }

  // ---- layer 1 ----
  selector_kernel<<<Bsz / 8, 256>>>(x, S1, sb1, p1, INs);
  expand_scale_kernel<<<(Bsz * (INs / 4)) / 256, 256>>>(
      (const float4*)x, p1, (float4*)xe, INs / 4);
  tc_gemm<true, true, false><<<dim3(H1s / 128, Bsz / 128), 256, SMEM_DYN>>>(
      H1s, Pex * INs, xe, w1r, p1, b1, h1);

  // ---- layer 2 ----
  selector_kernel<<<Bsz / 8, 256>>>(h1, S2, sb2, p2, H1s);
  expand_scale_kernel<<<(Bsz * (H1s / 4)) / 256, 256>>>(
      (const float4*)h1, p2, (float4*)h1e, H1s / 4);
  tc_gemm<true, true, true><<<dim3(H2s / 128, Bsz / 128), 256, SMEM_DYN>>>(
      H2s, Pex * H1s, h1e, w2r, p2, b2, h2);

  // ---- classifier ----
  tc_gemm<false, false, false><<<dim3(OUTs / 128, Bsz / 128), 256, SMEM_DYN>>>(
      OUTs, H2s, h2, wcr, nullptr, bc, out);
}

// round 7
// speedup vs baseline: 1.3081x; 1.3081x over previous
#include <cuda_runtime.h>
#include <cstdint>

#define Bsz  8192
#define INs  1024
#define H1s  2048
#define H2s  2048
#define OUTs 1024
#define Pex  8

// Scratch (device globals: allocation-free per harness rules)
__device__ float g_h1[(size_t)Bsz * H1s];            // 64 MB (relu+tf32-rounded)
__device__ float g_h2[(size_t)Bsz * H2s];            // 64 MB (relu+tf32-rounded)
__device__ float g_p1[(size_t)Bsz * Pex];
__device__ float g_p2[(size_t)Bsz * Pex];
__device__ float g_xr[(size_t)Bsz * INs];            // 32 MB (tf32-rounded x)
__device__ float g_w1r[(size_t)Pex * INs * H1s];     // 64 MB
__device__ float g_w2r[(size_t)Pex * H1s * H2s];     // 128 MB
__device__ float g_wcr[(size_t)H2s * OUTs];          // 8 MB

// ------------------------------ helpers ---------------------------------
__device__ __forceinline__ uint32_t smem_u32(const void* p) {
  uint32_t a;
  asm("{ .reg .u64 t; cvta.to.shared.u64 t, %1; cvt.u32.u64 %0, t; }"
      : "=r"(a) : "l"(p));
  return a;
}
__device__ __forceinline__ void cpa16(uint32_t s, const void* g) {
  asm volatile("cp.async.cg.shared.global [%0], [%1], 16;" :: "r"(s), "l"(g));
}
__device__ __forceinline__ void cpa_commit() {
  asm volatile("cp.async.commit_group;" ::: "memory");
}
template <int N>
__device__ __forceinline__ void cpa_wait() {
  asm volatile("cp.async.wait_group %0;" :: "n"(N) : "memory");
}
__device__ __forceinline__ uint32_t f2tf32(float f) {
  uint32_t u;
  asm("cvt.rna.tf32.f32 %0, %1;" : "=r"(u) : "f"(f));
  return u;
}
__device__ __forceinline__ float rtf(float f) {
  return __uint_as_float(f2tf32(f));
}
__device__ __forceinline__ void ldsm4(uint32_t (&r)[4], uint32_t a) {
  asm volatile("ldmatrix.sync.aligned.m8n8.x4.shared.b16 {%0,%1,%2,%3}, [%4];"
               : "=r"(r[0]), "=r"(r[1]), "=r"(r[2]), "=r"(r[3]) : "r"(a));
}
__device__ __forceinline__ void mma_t(float (&c)[4], const uint32_t (&a)[4],
                                      uint32_t b0, uint32_t b1) {
  asm volatile(
      "mma.sync.aligned.m16n8k8.row.col.f32.tf32.tf32.f32 "
      "{%0,%1,%2,%3}, {%4,%5,%6,%7}, {%8,%9}, {%0,%1,%2,%3};"
      : "+f"(c[0]), "+f"(c[1]), "+f"(c[2]), "+f"(c[3])
      : "r"(a[0]), "r"(a[1]), "r"(a[2]), "r"(a[3]), "r"(b0), "r"(b1));
}

// -------------------------------------------------------------------------
// tf32 pre-round pass (weights + x)
// -------------------------------------------------------------------------
__global__ void round_tf32_kernel(const float4* __restrict__ in,
                                  float4* __restrict__ out, int n4) {
  int i = blockIdx.x * blockDim.x + threadIdx.x;
  if (i < n4) {
    float4 v = in[i];
    v.x = rtf(v.x); v.y = rtf(v.y); v.z = rtf(v.z); v.w = rtf(v.w);
    out[i] = v;
  }
}

// -------------------------------------------------------------------------
// Selector: probs = softmax(X @ S + sb). One warp per 4 rows:
// S float4s loaded once per k-step, reused across the 4 rows.
// -------------------------------------------------------------------------
__global__ void selector_kernel(const float* __restrict__ X,
                                const float* __restrict__ S,
                                const float* __restrict__ sb,
                                float* __restrict__ probs, int K) {
  int gw = (blockIdx.x * blockDim.x + threadIdx.x) >> 5;
  int lane = threadIdx.x & 31;
  int row0 = gw * 4;
  int nvec = K >> 2;

  float acc[4][8];
#pragma unroll
  for (int r = 0; r < 4; r++)
#pragma unroll
    for (int p = 0; p < 8; p++) acc[r][p] = 0.f;

  for (int v = lane; v < nvec; v += 32) {
    const float4* Sv = reinterpret_cast<const float4*>(S + ((size_t)v << 2) * 8);
    float4 s0 = Sv[0], s1 = Sv[1], s2 = Sv[2], s3 = Sv[3];
    float4 s4 = Sv[4], s5 = Sv[5], s6 = Sv[6], s7 = Sv[7];
#pragma unroll
    for (int r = 0; r < 4; r++) {
      float4 x4 = reinterpret_cast<const float4*>(X + (size_t)(row0 + r) * K)[v];
      acc[r][0] += x4.x * s0.x + x4.y * s2.x + x4.z * s4.x + x4.w * s6.x;
      acc[r][1] += x4.x * s0.y + x4.y * s2.y + x4.z * s4.y + x4.w * s6.y;
      acc[r][2] += x4.x * s0.z + x4.y * s2.z + x4.z * s4.z + x4.w * s6.z;
      acc[r][3] += x4.x * s0.w + x4.y * s2.w + x4.z * s4.w + x4.w * s6.w;
      acc[r][4] += x4.x * s1.x + x4.y * s3.x + x4.z * s5.x + x4.w * s7.x;
      acc[r][5] += x4.x * s1.y + x4.y * s3.y + x4.z * s5.y + x4.w * s7.y;
      acc[r][6] += x4.x * s1.z + x4.y * s3.z + x4.z * s5.z + x4.w * s7.z;
      acc[r][7] += x4.x * s1.w + x4.y * s3.w + x4.z * s5.w + x4.w * s7.w;
    }
  }
#pragma unroll
  for (int off = 16; off; off >>= 1)
#pragma unroll
    for (int r = 0; r < 4; r++)
#pragma unroll
      for (int p = 0; p < 8; p++)
        acc[r][p] += __shfl_xor_sync(0xffffffffu, acc[r][p], off);

  if (lane < 4) {
    int r = lane;
    float a[8];
    float m = -1e30f;
#pragma unroll
    for (int p = 0; p < 8; p++) { a[p] = acc[r][p] + sb[p]; m = fmaxf(m, a[p]); }
    float s = 0.f;
#pragma unroll
    for (int p = 0; p < 8; p++) { a[p] = __expf(a[p] - m); s += a[p]; }
    float inv = 1.f / s;
#pragma unroll
    for (int p = 0; p < 8; p++) probs[(size_t)(row0 + r) * 8 + p] = a[p] * inv;
  }
}

// -------------------------------------------------------------------------
// mma.sync tf32 GEMM, tile 128x128x32, 3-stage cp.async, 8 warps (64x32).
//   MOE: compact A (x reused across experts via k&MASK); probs applied via
//        accumulator rescale at expert boundaries (mainloop is plain MMA).
//   RR : relu + tf32-round at store (hidden layers).
// -------------------------------------------------------------------------
template <bool MOE, bool RR, int LOG_IN>
__global__ __launch_bounds__(256, 2) void tc_gemm(
    int N, int K,
    const float* __restrict__ X, const float* __restrict__ W,
    const float* __restrict__ probs, const float* __restrict__ bias,
    float* __restrict__ C) {
  constexpr int NST = 3;
  constexpr int BROW_F = 136;                         // pad: mod 32 = 8 → no conflicts
  constexpr int BSTART_F = 4096;                      // A: 128*32 floats
  constexpr int SSTRIDE_F = BSTART_F + 32 * BROW_F;   // 8448 floats/stage
  constexpr int LDA = 1 << LOG_IN;
  constexpr int MASK = LDA - 1;
  constexpr int CPE = LDA / 32;                       // chunks per expert

  extern __shared__ float smf[];
  __shared__ float probs_s[128][8];
  __shared__ float bias_s[8][128];

  const int tid = threadIdx.x, lane = tid & 31, wid = tid >> 5;
  const int wm = wid >> 2, wn = wid & 3;
  const int m0 = blockIdx.y * 128, n0 = blockIdx.x * 128;
  const uint32_t sbase = smem_u32(smf);

  if (MOE) {
    for (int i = tid; i < 1024; i += 256) {
      int r = i >> 3, p = i & 7;
      probs_s[r][p] = probs[(size_t)(m0 + r) * 8 + p];
    }
    for (int i = tid; i < 1024; i += 256) {
      int p = i >> 7, c = i & 127;
      bias_s[p][c] = bias[(size_t)p * N + n0 + c];
    }
  } else {
    if (tid < 128) bias_s[0][tid] = bias[n0 + tid];
  }

  const int nchunk = K >> 5;

  auto issue = [&](int c, int st) {
    const int k0 = c << 5;
    const uint32_t sA = sbase + (uint32_t)st * (SSTRIDE_F * 4);
    const uint32_t sB = sA + BSTART_F * 4;
    const float* ab = X + (k0 & MASK);
#pragma unroll
    for (int i = 0; i < 4; i++) {          // A: 128 x 32, SW128 swizzle
      int f = tid + i * 256;
      int m = f >> 3, g = f & 7;
      cpa16(sA + (uint32_t)(m * 128 + ((g ^ (m & 7)) << 4)),
            ab + (size_t)(m0 + m) * LDA + g * 4);
    }
#pragma unroll
    for (int i = 0; i < 4; i++) {          // B: 32 x 128, pad-136 rows
      int f = tid + i * 256;
      int k = f >> 5, nc = f & 31;
      cpa16(sB + (uint32_t)(k * (BROW_F * 4) + nc * 16),
            W + (size_t)(k0 + k) * N + n0 + nc * 4);
    }
    cpa_commit();
  };

  float cacc[4][4][4];
#pragma unroll
  for (int a = 0; a < 4; a++)
#pragma unroll
    for (int b = 0; b < 4; b++)
#pragma unroll
      for (int d = 0; d < 4; d++) cacc[a][b][d] = 0.f;

  // ldmatrix per-thread address components
  const int q = lane >> 3, r8v = lane & 7, qh = q >> 1;
  uint32_t arow[4];
  int arow7[4];
#pragma unroll
  for (int mt = 0; mt < 4; mt++) {
    int r = wm * 64 + mt * 16 + (q & 1) * 8 + r8v;
    arow[mt] = (uint32_t)r * 128u;
    arow7[mt] = r & 7;
  }
  const int grp = lane >> 2, tig = lane & 3;

  float pr_lo[4], pr_hi[4];

  issue(0, 0);
  issue(1, 1);

  int st = 0;
  for (int c = 0; c < nchunk; c++) {
    cpa_wait<1>();
    __syncthreads();
    {
      int cn = c + 2;
      if (cn < nchunk) {
        int stn = st + 2; if (stn >= NST) stn -= NST;
        issue(cn, stn);
      } else {
        cpa_commit();
      }
    }

    if (MOE && (c & (CPE - 1)) == 0) {
      // expert boundary: rescale accumulator by pr_old/pr_new (registers only)
      const int p = c >> (LOG_IN - 5);
#pragma unroll
      for (int mt = 0; mt < 4; mt++) {
        int r = wm * 64 + mt * 16 + grp;
        float nlo = probs_s[r][p], nhi = probs_s[r + 8][p];
        if (c) {
          float rlo = pr_lo[mt] / nlo, rhi = pr_hi[mt] / nhi;
#pragma unroll
          for (int nt = 0; nt < 4; nt++) {
            cacc[mt][nt][0] *= rlo; cacc[mt][nt][1] *= rlo;
            cacc[mt][nt][2] *= rhi; cacc[mt][nt][3] *= rhi;
          }
        }
        pr_lo[mt] = nlo; pr_hi[mt] = nhi;
      }
    }

    const uint32_t sA = sbase + (uint32_t)st * (SSTRIDE_F * 4);
    const float* sBf = smf + st * SSTRIDE_F + BSTART_F;
#pragma unroll
    for (int ks = 0; ks < 4; ks++) {
      uint32_t af[4][4];
#pragma unroll
      for (int mt = 0; mt < 4; mt++)
        ldsm4(af[mt], sA + arow[mt] +
                          (uint32_t)(((ks * 2 + qh) ^ arow7[mt]) << 4));
      uint32_t bf[4][2];
#pragma unroll
      for (int nt = 0; nt < 4; nt++) {
        int n = wn * 32 + nt * 8 + grp;
        bf[nt][0] = __float_as_uint(sBf[(ks * 8 + tig) * BROW_F + n]);
        bf[nt][1] = __float_as_uint(sBf[(ks * 8 + tig + 4) * BROW_F + n]);
      }
#pragma unroll
      for (int mt = 0; mt < 4; mt++)
#pragma unroll
        for (int nt = 0; nt < 4; nt++)
          mma_t(cacc[mt][nt], af[mt], bf[nt][0], bf[nt][1]);
    }
    st++; if (st >= NST) st = 0;
  }

  if (MOE) {
    // final scale by pr_last
#pragma unroll
    for (int mt = 0; mt < 4; mt++)
#pragma unroll
      for (int nt = 0; nt < 4; nt++) {
        cacc[mt][nt][0] *= pr_lo[mt]; cacc[mt][nt][1] *= pr_lo[mt];
        cacc[mt][nt][2] *= pr_hi[mt]; cacc[mt][nt][3] *= pr_hi[mt];
      }
  }

  // ---- epilogue ----
#pragma unroll
  for (int mt = 0; mt < 4; mt++) {
#pragma unroll
    for (int half = 0; half < 2; half++) {
      int r = wm * 64 + mt * 16 + grp + half * 8;
      int m = m0 + r;
      float prr[8];
      if (MOE) {
#pragma unroll
        for (int p = 0; p < 8; p++) prr[p] = probs_s[r][p];
      }
#pragma unroll
      for (int nt = 0; nt < 4; nt++) {
        int nloc = wn * 32 + nt * 8 + tig * 2;
        float v0 = cacc[mt][nt][half * 2 + 0];
        float v1 = cacc[mt][nt][half * 2 + 1];
        if (MOE) {
          float cb0 = 0.f, cb1 = 0.f;
#pragma unroll
          for (int p = 0; p < 8; p++) {
            cb0 += prr[p] * bias_s[p][nloc];
            cb1 += prr[p] * bias_s[p][nloc + 1];
          }
          v0 += cb0; v1 += cb1;
        } else {
          v0 += bias_s[0][nloc];
          v1 += bias_s[0][nloc + 1];
        }
        if (RR) {
          v0 = rtf(fmaxf(v0, 0.f));
          v1 = rtf(fmaxf(v1, 0.f));
        }
        float2 o; o.x = v0; o.y = v1;
        *reinterpret_cast<float2*>(&C[(size_t)m * N + n0 + nloc]) = o;
      }
    }
  }
}

// -------------------------------------------------------------------------
extern "C" void kernel_launch(void* const* d_in, const int* in_sizes, int n_in,
                              void* d_out, int out_size) {
  const float* x   = (const float*)d_in[0];
  const float* W1  = (const float*)d_in[1];
  const float* b1  = (const float*)d_in[2];
  const float* S1  = (const float*)d_in[3];
  const float* sb1 = (const float*)d_in[4];
  const float* W2  = (const float*)d_in[5];
  const float* b2  = (const float*)d_in[6];
  const float* S2  = (const float*)d_in[7];
  const float* sb2 = (const float*)d_in[8];
  const float* Wc  = (const float*)d_in[9];
  const float* bc  = (const float*)d_in[10];
  float* out = (float*)d_out;

  float *h1, *h2, *p1, *p2, *xr, *w1r, *w2r, *wcr;
  cudaGetSymbolAddress((void**)&h1, g_h1);
  cudaGetSymbolAddress((void**)&h2, g_h2);
  cudaGetSymbolAddress((void**)&p1, g_p1);
  cudaGetSymbolAddress((void**)&p2, g_p2);
  cudaGetSymbolAddress((void**)&xr, g_xr);
  cudaGetSymbolAddress((void**)&w1r, g_w1r);
  cudaGetSymbolAddress((void**)&w2r, g_w2r);
  cudaGetSymbolAddress((void**)&wcr, g_wcr);

  const int SMEM_DYN = 3 * 8448 * 4;   // 101376 B
  cudaFuncSetAttribute(tc_gemm<true, true, 10>,
                       cudaFuncAttributeMaxDynamicSharedMemorySize, SMEM_DYN);
  cudaFuncSetAttribute(tc_gemm<true, true, 11>,
                       cudaFuncAttributeMaxDynamicSharedMemorySize, SMEM_DYN);
  cudaFuncSetAttribute(tc_gemm<false, false, 11>,
                       cudaFuncAttributeMaxDynamicSharedMemorySize, SMEM_DYN);

  // tf32 pre-round (RNA) of GEMM operands
  {
    int n4;
    n4 = (Bsz * INs) / 4;
    round_tf32_kernel<<<n4 / 256, 256>>>((const float4*)x, (float4*)xr, n4);
    n4 = (Pex * INs * H1s) / 4;
    round_tf32_kernel<<<n4 / 256, 256>>>((const float4*)W1, (float4*)w1r, n4);
    n4 = (Pex * H1s * H2s) / 4;
    round_tf32_kernel<<<n4 / 256, 256>>>((const float4*)W2, (float4*)w2r, n4);
    n4 = (H2s * OUTs) / 4;
    round_tf32_kernel<<<n4 / 256, 256>>>((const float4*)Wc, (float4*)wcr, n4);
  }

  // ---- layer 1 ----
  selector_kernel<<<Bsz / 32, 256>>>(x, S1, sb1, p1, INs);
  tc_gemm<true, true, 10><<<dim3(H1s / 128, Bsz / 128), 256, SMEM_DYN>>>(
      H1s, Pex * INs, xr, w1r, p1, b1, h1);

  // ---- layer 2 ----
  selector_kernel<<<Bsz / 32, 256>>>(h1, S2, sb2, p2, H1s);
  tc_gemm<true, true, 11><<<dim3(H2s / 128, Bsz / 128), 256, SMEM_DYN>>>(
      H2s, Pex * H1s, h1, w2r, p2, b2, h2);

  // ---- classifier ----
  tc_gemm<false, false, 11><<<dim3(OUTs / 128, Bsz / 128), 256, SMEM_DYN>>>(
      OUTs, H2s, h2, wcr, nullptr, bc, out);
}